// round 6
// baseline (speedup 1.0000x reference)
#include <cuda_runtime.h>

// Problem constants (fixed by setup_inputs): B=2, t=5, C=16, G=64
#define G 64
#define GG 4096
#define GGG 262144
#define NCH 16
#define CVOL (NCH * GGG)   // 4,194,304 floats per (C,D,H,W) frame
#define NPAIR 8

// smem tile: up to 16 z-planes x 16 y-rows x 24 x-floats (x window 4-aligned).
// XPITCH=24: warp's 4 y-rows hit disjoint 8-bank ranges -> conflict-free LDS.
#define XPITCH 24
#define ZSTRIDE (16 * XPITCH)       // 384
#define TILE_FLOATS (16 * ZSTRIDE)  // 6144 floats = 24.6 KB

// Per-pair fused affine map: f_i = M[i*4+0]*x + M[i*4+1]*y + M[i*4+2]*z + M[i*4+3]
__device__ float g_M[NPAIR][12];

__global__ void xform_kernel(const float* __restrict__ poses /* (2,5,4,4) */) {
    int n = threadIdx.x;
    if (n >= NPAIR) return;
    int b = n >> 2;
    int k = (n & 3) + 1;
    const float* P0 = poses + (size_t)(b * 5 + 0) * 16;
    const float* P1 = poses + (size_t)(b * 5 + k) * 16;

    // T = P0 @ inv(P1); P1 rigid => inv(P1) = [R1^T | -R1^T t1]
    float R[3][3], t[3];
#pragma unroll
    for (int i = 0; i < 3; i++)
#pragma unroll
        for (int j = 0; j < 3; j++)
            R[i][j] = P0[i * 4 + 0] * P1[j * 4 + 0]
                    + P0[i * 4 + 1] * P1[j * 4 + 1]
                    + P0[i * 4 + 2] * P1[j * 4 + 2];
#pragma unroll
    for (int i = 0; i < 3; i++)
        t[i] = P0[i * 4 + 3]
             - (R[i][0] * P1[3] + R[i][1] * P1[7] + R[i][2] * P1[11]);

    const float inv_m = 128.0f / 63.0f;
    const float s = 64.0f / 63.0f;
#pragma unroll
    for (int i = 0; i < 3; i++) {
        g_M[n][i * 4 + 0] = s * R[i][0];
        g_M[n][i * 4 + 1] = s * R[i][1];
        g_M[n][i * 4 + 2] = s * R[i][2];
        g_M[n][i * 4 + 3] =
            32.0f * (t[i] * inv_m - (R[i][0] + R[i][1] + R[i][2])) + 31.5f;
    }
}

// blockIdx.z in [0,64): warp tiles (8 z-tiles x 8 pairs).
// blockIdx.z in [64,72): frame-0 copy blocks (512), overlapping DRAM copy
// with the L1-bound warp work.
__global__ __launch_bounds__(256) void warp_kernel(const float* __restrict__ vox,
                                                   float* __restrict__ out) {
    const int tid = threadIdx.x;

    if (blockIdx.z >= 64) {
        // ---- copy path: out[b,0] = vox[b,0] for b=0,1
        int cb = ((int)blockIdx.z - 64) * 64 + (int)blockIdx.y * 8 + (int)blockIdx.x;
        int batch = cb >> 8;
        int local = cb & 255;
        const float4* s4 = (const float4*)(vox + (size_t)batch * 5 * CVOL);
        float4* d4 = (float4*)(out + (size_t)batch * 5 * CVOL);
        int base = local * 4096 + tid;
#pragma unroll
        for (int i = 0; i < 16; i++)
            d4[base + i * 256] = s4[base + i * 256];
        return;
    }

    const int n = blockIdx.z >> 3;  // pair 0..7

    __shared__ float Ms[12];
    __shared__ int sO[3], sD[3];
    __shared__ int sSkip;
    __shared__ __align__(16) float tile[TILE_FLOATS];

    if (tid < 12) Ms[tid] = g_M[n][tid];
    __syncthreads();

    const int bx0 = (int)blockIdx.x * 8;
    const int by0 = (int)blockIdx.y * 8;
    const int bz0 = (int)(blockIdx.z & 7) * 8;

    if (tid == 0) {
        int skip = 0;
#pragma unroll
        for (int i = 0; i < 3; i++) {
            float a = Ms[i * 4 + 0], b = Ms[i * 4 + 1], c = Ms[i * 4 + 2], d = Ms[i * 4 + 3];
            float xl = (float)bx0, xh = (float)(bx0 + 7);
            float yl = (float)by0, yh = (float)(by0 + 7);
            float zl = (float)bz0, zh = (float)(bz0 + 7);
            float fmin = d + fminf(a * xl, a * xh) + fminf(b * yl, b * yh) + fminf(c * zl, c * zh);
            float fmax = d + fmaxf(a * xl, a * xh) + fmaxf(b * yl, b * yh) + fmaxf(c * zl, c * zh);
            int o = (int)floorf(fmin);
            int dd = (int)floorf(fmax) + 2 - o;  // covers floor(min)..floor(max)+1 (<=15)
            if (dd > 16) dd = 16;                // safety
            sO[i] = o;
            sD[i] = dd;
            skip |= (o > 63) | (o + dd <= 0);
        }
        sSkip = skip;
    }
    __syncthreads();

    const int b = n >> 2, k = n & 3;
    const int frame = b * 5 + 1 + k;
    const float* __restrict__ src = vox + (size_t)frame * CVOL;
    float* __restrict__ dstf = out + (size_t)frame * CVOL;

    const int lx = bx0 + (tid & 7);
    const int ly = by0 + ((tid >> 3) & 7);
    const int lz = bz0 + (tid >> 6);  // p=0: z, p=1: z+4
    const int dst0 = lz * GG + ly * G + lx;

    if (sSkip) {
#pragma unroll
        for (int c = 0; c < NCH; c++) {
            dstf[dst0 + c * GGG] = 0.0f;
            dstf[dst0 + 4 * GG + c * GGG] = 0.0f;
        }
        return;
    }

    const int ox = sO[0], oy = sO[1], oz = sO[2];
    const int dx = sD[0], dy = sD[1], dz = sD[2];
    const int xfrac = ox & 3;
    const int ox4 = ox - xfrac;             // 4-aligned x window base
    const int nseg = (xfrac + dx + 3) >> 2; // <= 5 float4 segments per row

    // ---- per-point weights & smem base offsets (computed ONCE, reused over 16 ch)
    float wzy[2][4], wxa[2][2];
    int soff[2];
#pragma unroll
    for (int p = 0; p < 2; p++) {
        float xf = (float)lx, yf = (float)ly, zf = (float)(lz + p * 4);
        float fx = fmaf(Ms[2], zf, fmaf(Ms[1], yf, fmaf(Ms[0], xf, Ms[3])));
        float fy = fmaf(Ms[6], zf, fmaf(Ms[5], yf, fmaf(Ms[4], xf, Ms[7])));
        float fz = fmaf(Ms[10], zf, fmaf(Ms[9], yf, fmaf(Ms[8], xf, Ms[11])));
        float xfl = floorf(fx), yfl = floorf(fy), zfl = floorf(fz);
        float tx = fx - xfl, ty = fy - yfl, tz = fz - zfl;
        int ix0 = (int)xfl, iy0 = (int)yfl, iz0 = (int)zfl;

        float wx0 = ((unsigned)ix0 < 64u) ? (1.0f - tx) : 0.0f;
        float wx1 = ((unsigned)(ix0 + 1) < 64u) ? tx : 0.0f;
        float wy0 = ((unsigned)iy0 < 64u) ? (1.0f - ty) : 0.0f;
        float wy1 = ((unsigned)(iy0 + 1) < 64u) ? ty : 0.0f;
        float wz0 = ((unsigned)iz0 < 64u) ? (1.0f - tz) : 0.0f;
        float wz1 = ((unsigned)(iz0 + 1) < 64u) ? tz : 0.0f;

        wzy[p][0] = wz0 * wy0; wzy[p][1] = wz0 * wy1;
        wzy[p][2] = wz1 * wy0; wzy[p][3] = wz1 * wy1;
        wxa[p][0] = wx0; wxa[p][1] = wx1;

        soff[p] = (iz0 - oz) * ZSTRIDE + (iy0 - oy) * XPITCH + (ix0 - ox4);
    }

    // ---- precompute staging addresses (channel-invariant): dz*dy rows x nseg f4
    // Segments 4-aligned in x: fully in-range-x or fully OOB-x (zero weight).
    // Clamp y,z to [0,63] and linear offset to [0, GGG-4] for address safety
    // (all candidates are multiples of 4, preserving 16B alignment).
    int lin[5], sof[5];
    bool act[5];
    const int rowlen = dy * nseg;
    const int total = dz * rowlen;
#pragma unroll
    for (int i = 0; i < 5; i++) {
        int idx = tid + i * 256;
        act[i] = idx < total;
        int zi = idx / rowlen;
        int r = idx - zi * rowlen;
        int yi = r / nseg;
        int s = r - yi * nseg;
        int zc = min(max(oz + zi, 0), 63);
        int yc = min(max(oy + yi, 0), 63);
        int l = zc * GG + yc * G + (ox4 + 4 * s);
        lin[i] = min(max(l, 0), GGG - 4);
        sof[i] = zi * ZSTRIDE + yi * XPITCH + 4 * s;
    }

#pragma unroll 1
    for (int c = 0; c < NCH; c++) {
        const float* __restrict__ sc = src + c * GGG;
        __syncthreads();  // previous channel's readers done
#pragma unroll
        for (int i = 0; i < 5; i++) {
            if (act[i]) {
                float4 v = __ldg((const float4*)(sc + lin[i]));
                *(float4*)&tile[sof[i]] = v;
            }
        }
        __syncthreads();

#pragma unroll
        for (int p = 0; p < 2; p++) {
            const int s = soff[p];
            float t0 = fmaf(wxa[p][1], tile[s + 1], wxa[p][0] * tile[s]);
            float t1 = fmaf(wxa[p][1], tile[s + XPITCH + 1], wxa[p][0] * tile[s + XPITCH]);
            float t2 = fmaf(wxa[p][1], tile[s + ZSTRIDE + 1], wxa[p][0] * tile[s + ZSTRIDE]);
            float t3 = fmaf(wxa[p][1], tile[s + ZSTRIDE + XPITCH + 1],
                            wxa[p][0] * tile[s + ZSTRIDE + XPITCH]);
            float acc = wzy[p][0] * t0;
            acc = fmaf(wzy[p][1], t1, acc);
            acc = fmaf(wzy[p][2], t2, acc);
            acc = fmaf(wzy[p][3], t3, acc);
            dstf[dst0 + p * (4 * GG) + c * GGG] = acc;
        }
    }
}

extern "C" void kernel_launch(void* const* d_in, const int* in_sizes, int n_in,
                              void* d_out, int out_size) {
    const float* vox   = (const float*)d_in[0];   // (2,5,16,64,64,64) fp32
    const float* poses = (const float*)d_in[1];   // (2,5,4,4) fp32
    float* out = (float*)d_out;

    xform_kernel<<<1, 32>>>(poses);

    // z: 64 warp-tile slices (8 z-tiles x 8 pairs) + 8 copy slices (512 copy blocks)
    dim3 block(256, 1, 1);
    dim3 grid(8, 8, 72);
    warp_kernel<<<grid, block>>>(vox, out);
}

// round 7
// speedup vs baseline: 1.2066x; 1.2066x over previous
#include <cuda_runtime.h>

// Problem constants (fixed by setup_inputs): B=2, t=5, C=16, G=64
#define G 64
#define GG 4096
#define GGG 262144
#define NCH 16
#define CVOL (NCH * GGG)   // 4,194,304 floats per (C,D,H,W) frame
#define NPAIR 8

// smem tile: up to 16 z-planes x 16 y-rows x 24 x-floats (x window 4-aligned).
// XPITCH=24: a warp's 4 y-rows occupy disjoint 8-bank ranges (0,24,16,8).
// ZSTRIDE=388 (mod 32 = 4, multiple of 4): lanes differing in iz0 are offset
// by 4 banks instead of colliding; STS.128 alignment preserved.
#define XPITCH 24
#define ZSTRIDE 388
#define TILE_FLOATS (16 * ZSTRIDE)  // 6208 floats = 24.8 KB

// Per-pair fused affine map: f_i = M[i*4+0]*x + M[i*4+1]*y + M[i*4+2]*z + M[i*4+3]
__device__ float g_M[NPAIR][12];

__global__ void xform_kernel(const float* __restrict__ poses /* (2,5,4,4) */) {
    int n = threadIdx.x;
    if (n >= NPAIR) return;
    int b = n >> 2;
    int k = (n & 3) + 1;
    const float* P0 = poses + (size_t)(b * 5 + 0) * 16;
    const float* P1 = poses + (size_t)(b * 5 + k) * 16;

    // T = P0 @ inv(P1); P1 rigid => inv(P1) = [R1^T | -R1^T t1]
    float R[3][3], t[3];
#pragma unroll
    for (int i = 0; i < 3; i++)
#pragma unroll
        for (int j = 0; j < 3; j++)
            R[i][j] = P0[i * 4 + 0] * P1[j * 4 + 0]
                    + P0[i * 4 + 1] * P1[j * 4 + 1]
                    + P0[i * 4 + 2] * P1[j * 4 + 2];
#pragma unroll
    for (int i = 0; i < 3; i++)
        t[i] = P0[i * 4 + 3]
             - (R[i][0] * P1[3] + R[i][1] * P1[7] + R[i][2] * P1[11]);

    const float inv_m = 128.0f / 63.0f;
    const float s = 64.0f / 63.0f;
#pragma unroll
    for (int i = 0; i < 3; i++) {
        g_M[n][i * 4 + 0] = s * R[i][0];
        g_M[n][i * 4 + 1] = s * R[i][1];
        g_M[n][i * 4 + 2] = s * R[i][2];
        g_M[n][i * 4 + 3] =
            32.0f * (t[i] * inv_m - (R[i][0] + R[i][1] + R[i][2])) + 31.5f;
    }
}

// blockIdx.z in [0,64): warp tiles (8 z-tiles x 8 pairs).
// blockIdx.z in [64,72): frame-0 copy blocks (512), overlapping DRAM copy
// with the L1-bound warp work.
__global__ __launch_bounds__(256) void warp_kernel(const float* __restrict__ vox,
                                                   float* __restrict__ out) {
    const int tid = threadIdx.x;

    if (blockIdx.z >= 64) {
        // ---- copy path: out[b,0] = vox[b,0] for b=0,1
        int cb = ((int)blockIdx.z - 64) * 64 + (int)blockIdx.y * 8 + (int)blockIdx.x;
        int batch = cb >> 8;
        int local = cb & 255;
        const float4* s4 = (const float4*)(vox + (size_t)batch * 5 * CVOL);
        float4* d4 = (float4*)(out + (size_t)batch * 5 * CVOL);
        int base = local * 4096 + tid;
#pragma unroll
        for (int i = 0; i < 16; i++)
            d4[base + i * 256] = s4[base + i * 256];
        return;
    }

    const int n = blockIdx.z >> 3;  // pair 0..7

    __shared__ float Ms[12];
    __shared__ int sO[3], sD[3];
    __shared__ int sSkip;
    __shared__ __align__(16) float tile[TILE_FLOATS];

    if (tid < 12) Ms[tid] = g_M[n][tid];
    __syncthreads();

    const int bx0 = (int)blockIdx.x * 8;
    const int by0 = (int)blockIdx.y * 8;
    const int bz0 = (int)(blockIdx.z & 7) * 8;

    if (tid == 0) {
        int skip = 0;
#pragma unroll
        for (int i = 0; i < 3; i++) {
            float a = Ms[i * 4 + 0], b = Ms[i * 4 + 1], c = Ms[i * 4 + 2], d = Ms[i * 4 + 3];
            float xl = (float)bx0, xh = (float)(bx0 + 7);
            float yl = (float)by0, yh = (float)(by0 + 7);
            float zl = (float)bz0, zh = (float)(bz0 + 7);
            float fmin = d + fminf(a * xl, a * xh) + fminf(b * yl, b * yh) + fminf(c * zl, c * zh);
            float fmax = d + fmaxf(a * xl, a * xh) + fmaxf(b * yl, b * yh) + fmaxf(c * zl, c * zh);
            int o = (int)floorf(fmin);
            int dd = (int)floorf(fmax) + 2 - o;  // covers floor(min)..floor(max)+1 (<=15)
            if (dd > 16) dd = 16;                // safety
            sO[i] = o;
            sD[i] = dd;
            skip |= (o > 63) | (o + dd <= 0);
        }
        sSkip = skip;
    }
    __syncthreads();

    const int b = n >> 2, k = n & 3;
    const int frame = b * 5 + 1 + k;
    const float* __restrict__ src = vox + (size_t)frame * CVOL;
    float* __restrict__ dstf = out + (size_t)frame * CVOL;

    const int lx = bx0 + (tid & 7);
    const int ly = by0 + ((tid >> 3) & 7);
    const int lz = bz0 + (tid >> 6);  // p=0: z, p=1: z+4
    const int dst0 = lz * GG + ly * G + lx;

    if (sSkip) {
#pragma unroll
        for (int c = 0; c < NCH; c++) {
            dstf[dst0 + c * GGG] = 0.0f;
            dstf[dst0 + 4 * GG + c * GGG] = 0.0f;
        }
        return;
    }

    const int ox = sO[0], oy = sO[1], oz = sO[2];
    const int dx = sD[0], dy = sD[1], dz = sD[2];
    const int xfrac = ox & 3;
    const int ox4 = ox - xfrac;             // 4-aligned x window base
    const int nseg = (xfrac + dx + 3) >> 2; // <= 5 float4 segments per row

    // ---- per-point weights & smem base offsets (computed ONCE, reused over 16 ch)
    float wzy[2][4], wxa[2][2];
    int soff[2];
#pragma unroll
    for (int p = 0; p < 2; p++) {
        float xf = (float)lx, yf = (float)ly, zf = (float)(lz + p * 4);
        float fx = fmaf(Ms[2], zf, fmaf(Ms[1], yf, fmaf(Ms[0], xf, Ms[3])));
        float fy = fmaf(Ms[6], zf, fmaf(Ms[5], yf, fmaf(Ms[4], xf, Ms[7])));
        float fz = fmaf(Ms[10], zf, fmaf(Ms[9], yf, fmaf(Ms[8], xf, Ms[11])));
        float xfl = floorf(fx), yfl = floorf(fy), zfl = floorf(fz);
        float tx = fx - xfl, ty = fy - yfl, tz = fz - zfl;
        int ix0 = (int)xfl, iy0 = (int)yfl, iz0 = (int)zfl;

        float wx0 = ((unsigned)ix0 < 64u) ? (1.0f - tx) : 0.0f;
        float wx1 = ((unsigned)(ix0 + 1) < 64u) ? tx : 0.0f;
        float wy0 = ((unsigned)iy0 < 64u) ? (1.0f - ty) : 0.0f;
        float wy1 = ((unsigned)(iy0 + 1) < 64u) ? ty : 0.0f;
        float wz0 = ((unsigned)iz0 < 64u) ? (1.0f - tz) : 0.0f;
        float wz1 = ((unsigned)(iz0 + 1) < 64u) ? tz : 0.0f;

        wzy[p][0] = wz0 * wy0; wzy[p][1] = wz0 * wy1;
        wzy[p][2] = wz1 * wy0; wzy[p][3] = wz1 * wy1;
        wxa[p][0] = wx0; wxa[p][1] = wx1;

        soff[p] = (iz0 - oz) * ZSTRIDE + (iy0 - oy) * XPITCH + (ix0 - ox4);
    }

    // ---- precompute staging addresses (channel-invariant): dz*dy rows x nseg f4
    // Segments 4-aligned in x: fully in-range-x or fully OOB-x (zero weight).
    // Clamp y,z to [0,63] and linear offset to [0, GGG-4] for address safety
    // (all candidates are multiples of 4, preserving 16B alignment).
    int lin[5], sof[5];
    bool act[5];
    const int rowlen = dy * nseg;
    const int total = dz * rowlen;
#pragma unroll
    for (int i = 0; i < 5; i++) {
        int idx = tid + i * 256;
        act[i] = idx < total;
        int zi = idx / rowlen;
        int r = idx - zi * rowlen;
        int yi = r / nseg;
        int s = r - yi * nseg;
        int zc = min(max(oz + zi, 0), 63);
        int yc = min(max(oy + yi, 0), 63);
        int l = zc * GG + yc * G + (ox4 + 4 * s);
        lin[i] = min(max(l, 0), GGG - 4);
        sof[i] = zi * ZSTRIDE + yi * XPITCH + 4 * s;
    }

#pragma unroll 1
    for (int c = 0; c < NCH; c++) {
        const float* __restrict__ sc = src + c * GGG;
        __syncthreads();  // previous channel's readers done
#pragma unroll
        for (int i = 0; i < 5; i++) {
            if (act[i]) {
                float4 v = __ldg((const float4*)(sc + lin[i]));
                *(float4*)&tile[sof[i]] = v;
            }
        }
        __syncthreads();

#pragma unroll
        for (int p = 0; p < 2; p++) {
            const int s = soff[p];
            float t0 = fmaf(wxa[p][1], tile[s + 1], wxa[p][0] * tile[s]);
            float t1 = fmaf(wxa[p][1], tile[s + XPITCH + 1], wxa[p][0] * tile[s + XPITCH]);
            float t2 = fmaf(wxa[p][1], tile[s + ZSTRIDE + 1], wxa[p][0] * tile[s + ZSTRIDE]);
            float t3 = fmaf(wxa[p][1], tile[s + ZSTRIDE + XPITCH + 1],
                            wxa[p][0] * tile[s + ZSTRIDE + XPITCH]);
            float acc = wzy[p][0] * t0;
            acc = fmaf(wzy[p][1], t1, acc);
            acc = fmaf(wzy[p][2], t2, acc);
            acc = fmaf(wzy[p][3], t3, acc);
            dstf[dst0 + p * (4 * GG) + c * GGG] = acc;
        }
    }
}

extern "C" void kernel_launch(void* const* d_in, const int* in_sizes, int n_in,
                              void* d_out, int out_size) {
    const float* vox   = (const float*)d_in[0];   // (2,5,16,64,64,64) fp32
    const float* poses = (const float*)d_in[1];   // (2,5,4,4) fp32
    float* out = (float*)d_out;

    xform_kernel<<<1, 32>>>(poses);

    // z: 64 warp-tile slices (8 z-tiles x 8 pairs) + 8 copy slices (512 copy blocks)
    dim3 block(256, 1, 1);
    dim3 grid(8, 8, 72);
    warp_kernel<<<grid, block>>>(vox, out);
}